// round 1
// baseline (speedup 1.0000x reference)
#include <cuda_runtime.h>

#define N_USERS 100000
#define N_ITEMS 50000
#define N_NODES 150000
#define EMB     128
#define EMB4    32
#define NNZ     2400000
#define ALPHA   0.25f
#define SCAN_NB ((N_NODES + 255) / 256)   // 587

// ---------------- device scratch (static, no runtime allocation) ------------
__device__ __align__(16) float g_emb[4][(size_t)N_NODES * EMB]; // layer outputs
__device__ int   g_cnt[N_NODES];
__device__ int   g_off[N_NODES + 1];
__device__ int   g_fill[N_NODES];
__device__ int   g_bsum[SCAN_NB];
__device__ int   g_bscan[SCAN_NB];
__device__ int   g_ecol[NNZ];
__device__ float g_eval[NNZ];

// ---------------- init: concat embeddings, zero histogram -------------------
__global__ void k_init(const float4* __restrict__ ue, const float4* __restrict__ ie) {
    int i = blockIdx.x * blockDim.x + threadIdx.x;
    if (i < N_NODES) g_cnt[i] = 0;
    if (i >= N_NODES * EMB4) return;
    int node = i >> 5;
    float4 v = (node < N_USERS) ? ue[i] : ie[i - N_USERS * EMB4];
    reinterpret_cast<float4*>(g_emb[0])[i] = v;
}

// ---------------- CSR build: histogram -> scan -> scatter -------------------
__global__ void k_hist(const int* __restrict__ rows) {
    int e = blockIdx.x * blockDim.x + threadIdx.x;
    if (e < NNZ) atomicAdd(&g_cnt[rows[e]], 1);
}

__global__ void k_scan1() {
    __shared__ int s[256];
    int tid = threadIdx.x;
    int gid = blockIdx.x * 256 + tid;
    int v = (gid < N_NODES) ? g_cnt[gid] : 0;
    s[tid] = v;
    __syncthreads();
#pragma unroll
    for (int d = 1; d < 256; d <<= 1) {
        int t = (tid >= d) ? s[tid - d] : 0;
        __syncthreads();
        if (tid >= d) s[tid] += t;
        __syncthreads();
    }
    if (gid < N_NODES) g_off[gid] = s[tid] - v;      // block-local exclusive
    if (tid == 255) g_bsum[blockIdx.x] = s[255];
}

__global__ void k_scan2() {
    __shared__ int s[1024];
    int tid = threadIdx.x;
    int v = (tid < SCAN_NB) ? g_bsum[tid] : 0;
    s[tid] = v;
    __syncthreads();
    for (int d = 1; d < 1024; d <<= 1) {
        int t = (tid >= d) ? s[tid - d] : 0;
        __syncthreads();
        if (tid >= d) s[tid] += t;
        __syncthreads();
    }
    if (tid < SCAN_NB) g_bscan[tid] = s[tid] - v;    // exclusive block offsets
}

__global__ void k_scan3() {
    int gid = blockIdx.x * 256 + threadIdx.x;
    if (gid < N_NODES) {
        int o = g_off[gid] + g_bscan[blockIdx.x];
        g_off[gid]  = o;
        g_fill[gid] = o;
    }
    if (gid == 0) g_off[N_NODES] = NNZ;
}

__global__ void k_scatter(const int* __restrict__ rows, const int* __restrict__ cols,
                          const float* __restrict__ vals) {
    int e = blockIdx.x * blockDim.x + threadIdx.x;
    if (e >= NNZ) return;
    int p = atomicAdd(&g_fill[rows[e]], 1);
    g_ecol[p] = cols[e];
    g_eval[p] = vals[e];
}

// ---------------- SpMM: one warp per row, register accumulation -------------
__global__ void __launch_bounds__(256) k_spmm(int layer) {
    int gw   = (blockIdx.x * 256 + threadIdx.x) >> 5;
    int lane = threadIdx.x & 31;
    if (gw >= N_NODES) return;
    const float4* __restrict__ src = reinterpret_cast<const float4*>(g_emb[layer]);
    float4* __restrict__ dst       = reinterpret_cast<float4*>(g_emb[layer + 1]);
    int beg = g_off[gw], end = g_off[gw + 1];
    float4 acc = make_float4(0.f, 0.f, 0.f, 0.f);
    int e = beg;
    for (; e + 2 <= end; e += 2) {      // unroll 2 for MLP
        int   c0 = __ldg(&g_ecol[e]);
        int   c1 = __ldg(&g_ecol[e + 1]);
        float v0 = __ldg(&g_eval[e]);
        float v1 = __ldg(&g_eval[e + 1]);
        float4 x0 = src[(size_t)c0 * EMB4 + lane];
        float4 x1 = src[(size_t)c1 * EMB4 + lane];
        acc.x = fmaf(v0, x0.x, acc.x); acc.y = fmaf(v0, x0.y, acc.y);
        acc.z = fmaf(v0, x0.z, acc.z); acc.w = fmaf(v0, x0.w, acc.w);
        acc.x = fmaf(v1, x1.x, acc.x); acc.y = fmaf(v1, x1.y, acc.y);
        acc.z = fmaf(v1, x1.z, acc.z); acc.w = fmaf(v1, x1.w, acc.w);
    }
    if (e < end) {
        int   c0 = __ldg(&g_ecol[e]);
        float v0 = __ldg(&g_eval[e]);
        float4 x0 = src[(size_t)c0 * EMB4 + lane];
        acc.x = fmaf(v0, x0.x, acc.x); acc.y = fmaf(v0, x0.y, acc.y);
        acc.z = fmaf(v0, x0.z, acc.z); acc.w = fmaf(v0, x0.w, acc.w);
    }
    dst[(size_t)gw * EMB4 + lane] = acc;
}

// ---------------- outputs ----------------------------------------------------
// out layout (floats): [user_final 100000x128][item_final 50000x128]
//                      [masked_user 100000x128][predicted 100000x128][mask 100000x128]
#define O1_4 ((size_t)N_USERS * EMB4)                       // item_final
#define O2_4 ((size_t)N_NODES * EMB4)                       // masked_user
#define O3_4 (O2_4 + (size_t)N_USERS * EMB4)                // predicted
#define O4_4 (O3_4 + (size_t)N_USERS * EMB4)                // mask

__global__ void k_out(const float4* __restrict__ mask, float4* __restrict__ out) {
    int i = blockIdx.x * blockDim.x + threadIdx.x;
    if (i >= N_NODES * EMB4) return;
    float4 a = reinterpret_cast<const float4*>(g_emb[0])[i];
    float4 b = reinterpret_cast<const float4*>(g_emb[1])[i];
    float4 c = reinterpret_cast<const float4*>(g_emb[2])[i];
    float4 d = reinterpret_cast<const float4*>(g_emb[3])[i];
    float4 comb;
    comb.x = ALPHA * (a.x + b.x + c.x + d.x);
    comb.y = ALPHA * (a.y + b.y + c.y + d.y);
    comb.z = ALPHA * (a.z + b.z + c.z + d.z);
    comb.w = ALPHA * (a.w + b.w + c.w + d.w);
    const int U4 = N_USERS * EMB4;
    if (i < U4) {
        out[i] = comb;
        float4 m = mask[i];
        float4 mu = make_float4(comb.x * m.x, comb.y * m.y, comb.z * m.z, comb.w * m.w);
        out[O2_4 + i] = mu;
        out[O4_4 + i] = m;
    } else {
        out[O1_4 + (i - U4)] = comb;
    }
}

// ---------------- GEMM: predicted = relu(masked @ W + b) --------------------
__global__ void __launch_bounds__(256) k_gemm(const float* __restrict__ A,
                                              const float* __restrict__ W,
                                              const float* __restrict__ bias,
                                              float* __restrict__ C, int M) {
    __shared__ float As[32][68];    // [k][m], padded
    __shared__ float Ws[32][128];   // [k][n]
    int tid = threadIdx.x;
    int m_base = blockIdx.x * 64;
    int tx = tid & 15;      // n group: 8 cols each
    int ty = tid >> 4;      // m group: 4 rows each
    int n0 = tx * 8;
    int m0 = ty * 4;
    float acc[4][8];
#pragma unroll
    for (int i = 0; i < 4; i++)
#pragma unroll
        for (int j = 0; j < 8; j++) acc[i][j] = 0.f;

    for (int kk = 0; kk < 128; kk += 32) {
        int am = tid >> 3;              // 0..31
        int ak = (tid & 7) * 4;         // 0..28
#pragma unroll
        for (int p = 0; p < 2; p++) {
            int m  = am + p * 32;
            int gm = m_base + m;
            float4 v = (gm < M) ? *reinterpret_cast<const float4*>(&A[(size_t)gm * 128 + kk + ak])
                                : make_float4(0.f, 0.f, 0.f, 0.f);
            As[ak + 0][m] = v.x; As[ak + 1][m] = v.y;
            As[ak + 2][m] = v.z; As[ak + 3][m] = v.w;
        }
#pragma unroll
        for (int p = 0; p < 4; p++) {
            int idx = (tid + p * 256) * 4;
            int k = idx >> 7, n = idx & 127;
            *reinterpret_cast<float4*>(&Ws[k][n]) =
                *reinterpret_cast<const float4*>(&W[(size_t)(kk + k) * 128 + n]);
        }
        __syncthreads();
#pragma unroll
        for (int k = 0; k < 32; k++) {
            float4 a4 = *reinterpret_cast<float4*>(&As[k][m0]);
            float4 w0 = *reinterpret_cast<float4*>(&Ws[k][n0]);
            float4 w1 = *reinterpret_cast<float4*>(&Ws[k][n0 + 4]);
            float av[4] = {a4.x, a4.y, a4.z, a4.w};
            float wv[8] = {w0.x, w0.y, w0.z, w0.w, w1.x, w1.y, w1.z, w1.w};
#pragma unroll
            for (int i = 0; i < 4; i++)
#pragma unroll
                for (int j = 0; j < 8; j++)
                    acc[i][j] = fmaf(av[i], wv[j], acc[i][j]);
        }
        __syncthreads();
    }
    float bv[8];
#pragma unroll
    for (int j = 0; j < 8; j++) bv[j] = bias[n0 + j];
#pragma unroll
    for (int i = 0; i < 4; i++) {
        int gm = m_base + m0 + i;
        if (gm < M) {
            float4 r0, r1;
            r0.x = fmaxf(acc[i][0] + bv[0], 0.f); r0.y = fmaxf(acc[i][1] + bv[1], 0.f);
            r0.z = fmaxf(acc[i][2] + bv[2], 0.f); r0.w = fmaxf(acc[i][3] + bv[3], 0.f);
            r1.x = fmaxf(acc[i][4] + bv[4], 0.f); r1.y = fmaxf(acc[i][5] + bv[5], 0.f);
            r1.z = fmaxf(acc[i][6] + bv[6], 0.f); r1.w = fmaxf(acc[i][7] + bv[7], 0.f);
            *reinterpret_cast<float4*>(&C[(size_t)gm * 128 + n0])     = r0;
            *reinterpret_cast<float4*>(&C[(size_t)gm * 128 + n0 + 4]) = r1;
        }
    }
}

// ---------------- launch -----------------------------------------------------
extern "C" void kernel_launch(void* const* d_in, const int* in_sizes, int n_in,
                              void* d_out, int out_size) {
    const float* ue   = (const float*)d_in[0];
    const float* ie   = (const float*)d_in[1];
    const int*   rows = (const int*)  d_in[2];
    const int*   cols = (const int*)  d_in[3];
    const float* vals = (const float*)d_in[4];
    const float* mask = (const float*)d_in[5];
    const float* W    = (const float*)d_in[6];
    const float* bias = (const float*)d_in[7];
    float* out = (float*)d_out;

    int nthr = N_NODES * EMB4;  // 4.8M
    k_init<<<(nthr + 255) / 256, 256>>>((const float4*)ue, (const float4*)ie);
    k_hist<<<(NNZ + 255) / 256, 256>>>(rows);
    k_scan1<<<SCAN_NB, 256>>>();
    k_scan2<<<1, 1024>>>();
    k_scan3<<<SCAN_NB, 256>>>();
    k_scatter<<<(NNZ + 255) / 256, 256>>>(rows, cols, vals);
    for (int l = 0; l < 3; l++)
        k_spmm<<<(N_NODES * 32 + 255) / 256, 256>>>(l);
    k_out<<<(nthr + 255) / 256, 256>>>((const float4*)mask, (float4*)out);

    const float* Amasked = out + (size_t)N_NODES * EMB;
    float* Cpred = out + (size_t)N_NODES * EMB + (size_t)N_USERS * EMB;
    k_gemm<<<(N_USERS + 63) / 64, 256>>>(Amasked, W, bias, Cpred, N_USERS);
}

// round 3
// speedup vs baseline: 1.2061x; 1.2061x over previous
#include <cuda_runtime.h>
#include <cuda_bf16.h>

#define N_USERS 100000
#define N_ITEMS 50000
#define N_NODES 150000
#define EMB     128
#define EMB4    32
#define NNZ     2400000
#define ALPHA   0.25f
#define SCAN_NB ((N_NODES + 255) / 256)   // 587

// ---------------- device scratch (static, no runtime allocation) ------------
__device__ __align__(16) float          g_emb[3][(size_t)N_NODES * EMB];  // fp32 layers 0..2
__device__ __align__(16) __nv_bfloat16  g_embh[3][(size_t)N_NODES * EMB]; // bf16 gather copies
__device__ int   g_cnt[N_NODES];
__device__ int   g_off[N_NODES + 1];
__device__ int   g_fill[N_NODES];
__device__ int   g_bsum[SCAN_NB];
__device__ int   g_bscan[SCAN_NB];
__device__ uint2 g_edge[NNZ];             // (col, float-bits of val)

// ---------------- helpers ----------------------------------------------------
__device__ __forceinline__ void fma_bf16x4(uint2 u, float v, float4& acc) {
    __nv_bfloat162 b0 = *reinterpret_cast<const __nv_bfloat162*>(&u.x);
    __nv_bfloat162 b1 = *reinterpret_cast<const __nv_bfloat162*>(&u.y);
    float2 f0 = __bfloat1622float2(b0);
    float2 f1 = __bfloat1622float2(b1);
    acc.x = fmaf(v, f0.x, acc.x); acc.y = fmaf(v, f0.y, acc.y);
    acc.z = fmaf(v, f1.x, acc.z); acc.w = fmaf(v, f1.y, acc.w);
}

__device__ __forceinline__ uint2 pack_bf16x4(float4 a) {
    uint2 r;
    __nv_bfloat162 h0 = __floats2bfloat162_rn(a.x, a.y);
    __nv_bfloat162 h1 = __floats2bfloat162_rn(a.z, a.w);
    r.x = *reinterpret_cast<const unsigned*>(&h0);
    r.y = *reinterpret_cast<const unsigned*>(&h1);
    return r;
}

// ---------------- init: concat embeddings (fp32 + bf16), zero histogram -----
__global__ void k_init(const float4* __restrict__ ue, const float4* __restrict__ ie) {
    int i = blockIdx.x * blockDim.x + threadIdx.x;
    if (i < N_NODES) g_cnt[i] = 0;
    if (i >= N_NODES * EMB4) return;
    int node = i >> 5;
    float4 v = (node < N_USERS) ? ue[i] : ie[i - N_USERS * EMB4];
    reinterpret_cast<float4*>(g_emb[0])[i] = v;
    reinterpret_cast<uint2*>(g_embh[0])[i] = pack_bf16x4(v);
}

// ---------------- CSR build: histogram -> scan -> scatter -------------------
__global__ void k_hist(const int* __restrict__ rows) {
    int e = blockIdx.x * blockDim.x + threadIdx.x;
    if (e < NNZ) atomicAdd(&g_cnt[rows[e]], 1);
}

__global__ void k_scan1() {
    __shared__ int s[256];
    int tid = threadIdx.x;
    int gid = blockIdx.x * 256 + tid;
    int v = (gid < N_NODES) ? g_cnt[gid] : 0;
    s[tid] = v;
    __syncthreads();
#pragma unroll
    for (int d = 1; d < 256; d <<= 1) {
        int t = (tid >= d) ? s[tid - d] : 0;
        __syncthreads();
        if (tid >= d) s[tid] += t;
        __syncthreads();
    }
    if (gid < N_NODES) g_off[gid] = s[tid] - v;      // block-local exclusive
    if (tid == 255) g_bsum[blockIdx.x] = s[255];
}

__global__ void k_scan2() {
    __shared__ int s[1024];
    int tid = threadIdx.x;
    int v = (tid < SCAN_NB) ? g_bsum[tid] : 0;
    s[tid] = v;
    __syncthreads();
    for (int d = 1; d < 1024; d <<= 1) {
        int t = (tid >= d) ? s[tid - d] : 0;
        __syncthreads();
        if (tid >= d) s[tid] += t;
        __syncthreads();
    }
    if (tid < SCAN_NB) g_bscan[tid] = s[tid] - v;    // exclusive block offsets
}

__global__ void k_scan3() {
    int gid = blockIdx.x * 256 + threadIdx.x;
    if (gid < N_NODES) {
        int o = g_off[gid] + g_bscan[blockIdx.x];
        g_off[gid]  = o;
        g_fill[gid] = o;
    }
    if (gid == 0) g_off[N_NODES] = NNZ;
}

__global__ void k_scatter(const int* __restrict__ rows, const int* __restrict__ cols,
                          const float* __restrict__ vals) {
    int e = blockIdx.x * blockDim.x + threadIdx.x;
    if (e >= NNZ) return;
    int p = atomicAdd(&g_fill[rows[e]], 1);
    g_edge[p] = make_uint2((unsigned)cols[e], __float_as_uint(vals[e]));
}

// ---------------- SpMM (layers 0->1, 1->2): bf16 gather, fp32 accumulate ----
__global__ void __launch_bounds__(256) k_spmm(int layer) {
    int gw   = (blockIdx.x * 256 + threadIdx.x) >> 5;
    int lane = threadIdx.x & 31;
    if (gw >= N_NODES) return;
    const uint2* __restrict__ src = reinterpret_cast<const uint2*>(g_embh[layer]);
    int beg = g_off[gw], end = g_off[gw + 1];
    float4 acc = make_float4(0.f, 0.f, 0.f, 0.f);
    int e = beg;
    for (; e + 4 <= end; e += 4) {
        uint2 e0 = __ldg(&g_edge[e]);
        uint2 e1 = __ldg(&g_edge[e + 1]);
        uint2 e2 = __ldg(&g_edge[e + 2]);
        uint2 e3 = __ldg(&g_edge[e + 3]);
        uint2 x0 = src[(size_t)e0.x * EMB4 + lane];
        uint2 x1 = src[(size_t)e1.x * EMB4 + lane];
        uint2 x2 = src[(size_t)e2.x * EMB4 + lane];
        uint2 x3 = src[(size_t)e3.x * EMB4 + lane];
        fma_bf16x4(x0, __uint_as_float(e0.y), acc);
        fma_bf16x4(x1, __uint_as_float(e1.y), acc);
        fma_bf16x4(x2, __uint_as_float(e2.y), acc);
        fma_bf16x4(x3, __uint_as_float(e3.y), acc);
    }
    for (; e < end; e++) {
        uint2 ed = __ldg(&g_edge[e]);
        uint2 x  = src[(size_t)ed.x * EMB4 + lane];
        fma_bf16x4(x, __uint_as_float(ed.y), acc);
    }
    size_t ri = (size_t)gw * EMB4 + lane;
    reinterpret_cast<float4*>(g_emb[layer + 1])[ri] = acc;
    reinterpret_cast<uint2*>(g_embh[layer + 1])[ri] = pack_bf16x4(acc);
}

// ---------------- final: SpMM layer 2->3 fused with combine + outputs -------
// out layout (floats): [user_final 100000x128][item_final 50000x128]
//                      [masked_user 100000x128][predicted 100000x128][mask 100000x128]
// NOTE: user_final + item_final are contiguous => all nodes write out[ri].
#define O2_4 ((size_t)N_NODES * EMB4)                       // masked_user
#define O3_4 (O2_4 + (size_t)N_USERS * EMB4)                // predicted
#define O4_4 (O3_4 + (size_t)N_USERS * EMB4)                // mask

__global__ void __launch_bounds__(256) k_final(const float4* __restrict__ mask,
                                               float4* __restrict__ out) {
    int gw   = (blockIdx.x * 256 + threadIdx.x) >> 5;
    int lane = threadIdx.x & 31;
    if (gw >= N_NODES) return;
    const uint2* __restrict__ src = reinterpret_cast<const uint2*>(g_embh[2]);
    int beg = g_off[gw], end = g_off[gw + 1];
    float4 acc = make_float4(0.f, 0.f, 0.f, 0.f);
    int e = beg;
    for (; e + 4 <= end; e += 4) {
        uint2 e0 = __ldg(&g_edge[e]);
        uint2 e1 = __ldg(&g_edge[e + 1]);
        uint2 e2 = __ldg(&g_edge[e + 2]);
        uint2 e3 = __ldg(&g_edge[e + 3]);
        uint2 x0 = src[(size_t)e0.x * EMB4 + lane];
        uint2 x1 = src[(size_t)e1.x * EMB4 + lane];
        uint2 x2 = src[(size_t)e2.x * EMB4 + lane];
        uint2 x3 = src[(size_t)e3.x * EMB4 + lane];
        fma_bf16x4(x0, __uint_as_float(e0.y), acc);
        fma_bf16x4(x1, __uint_as_float(e1.y), acc);
        fma_bf16x4(x2, __uint_as_float(e2.y), acc);
        fma_bf16x4(x3, __uint_as_float(e3.y), acc);
    }
    for (; e < end; e++) {
        uint2 ed = __ldg(&g_edge[e]);
        uint2 x  = src[(size_t)ed.x * EMB4 + lane];
        fma_bf16x4(x, __uint_as_float(ed.y), acc);
    }
    size_t ri = (size_t)gw * EMB4 + lane;
    float4 a = reinterpret_cast<const float4*>(g_emb[0])[ri];
    float4 b = reinterpret_cast<const float4*>(g_emb[1])[ri];
    float4 c = reinterpret_cast<const float4*>(g_emb[2])[ri];
    float4 comb;
    comb.x = ALPHA * (a.x + b.x + c.x + acc.x);
    comb.y = ALPHA * (a.y + b.y + c.y + acc.y);
    comb.z = ALPHA * (a.z + b.z + c.z + acc.z);
    comb.w = ALPHA * (a.w + b.w + c.w + acc.w);
    out[ri] = comb;                    // user_final / item_final (contiguous)
    if (gw < N_USERS) {
        float4 m = mask[ri];
        float4 mu = make_float4(comb.x * m.x, comb.y * m.y, comb.z * m.z, comb.w * m.w);
        out[O2_4 + ri] = mu;
        out[O4_4 + ri] = m;
    }
}

// ---------------- GEMM: predicted = relu(masked @ W + b) --------------------
__global__ void __launch_bounds__(256) k_gemm(const float* __restrict__ A,
                                              const float* __restrict__ W,
                                              const float* __restrict__ bias,
                                              float* __restrict__ C, int M) {
    __shared__ float As[32][68];    // [k][m], padded
    __shared__ float Ws[32][128];   // [k][n]
    int tid = threadIdx.x;
    int m_base = blockIdx.x * 64;
    int tx = tid & 15;      // n group: 8 cols each
    int ty = tid >> 4;      // m group: 4 rows each
    int n0 = tx * 8;
    int m0 = ty * 4;
    float acc[4][8];
#pragma unroll
    for (int i = 0; i < 4; i++)
#pragma unroll
        for (int j = 0; j < 8; j++) acc[i][j] = 0.f;

    for (int kk = 0; kk < 128; kk += 32) {
        int am = tid >> 3;              // 0..31
        int ak = (tid & 7) * 4;         // 0..28
#pragma unroll
        for (int p = 0; p < 2; p++) {
            int m  = am + p * 32;
            int gm = m_base + m;
            float4 v = (gm < M) ? *reinterpret_cast<const float4*>(&A[(size_t)gm * 128 + kk + ak])
                                : make_float4(0.f, 0.f, 0.f, 0.f);
            As[ak + 0][m] = v.x; As[ak + 1][m] = v.y;
            As[ak + 2][m] = v.z; As[ak + 3][m] = v.w;
        }
#pragma unroll
        for (int p = 0; p < 4; p++) {
            int idx = (tid + p * 256) * 4;
            int k = idx >> 7, n = idx & 127;
            *reinterpret_cast<float4*>(&Ws[k][n]) =
                *reinterpret_cast<const float4*>(&W[(size_t)(kk + k) * 128 + n]);
        }
        __syncthreads();
#pragma unroll
        for (int k = 0; k < 32; k++) {
            float4 a4 = *reinterpret_cast<float4*>(&As[k][m0]);
            float4 w0 = *reinterpret_cast<float4*>(&Ws[k][n0]);
            float4 w1 = *reinterpret_cast<float4*>(&Ws[k][n0 + 4]);
            float av[4] = {a4.x, a4.y, a4.z, a4.w};
            float wv[8] = {w0.x, w0.y, w0.z, w0.w, w1.x, w1.y, w1.z, w1.w};
#pragma unroll
            for (int i = 0; i < 4; i++)
#pragma unroll
                for (int j = 0; j < 8; j++)
                    acc[i][j] = fmaf(av[i], wv[j], acc[i][j]);
        }
        __syncthreads();
    }
    float bv[8];
#pragma unroll
    for (int j = 0; j < 8; j++) bv[j] = bias[n0 + j];
#pragma unroll
    for (int i = 0; i < 4; i++) {
        int gm = m_base + m0 + i;
        if (gm < M) {
            float4 r0, r1;
            r0.x = fmaxf(acc[i][0] + bv[0], 0.f); r0.y = fmaxf(acc[i][1] + bv[1], 0.f);
            r0.z = fmaxf(acc[i][2] + bv[2], 0.f); r0.w = fmaxf(acc[i][3] + bv[3], 0.f);
            r1.x = fmaxf(acc[i][4] + bv[4], 0.f); r1.y = fmaxf(acc[i][5] + bv[5], 0.f);
            r1.z = fmaxf(acc[i][6] + bv[6], 0.f); r1.w = fmaxf(acc[i][7] + bv[7], 0.f);
            *reinterpret_cast<float4*>(&C[(size_t)gm * 128 + n0])     = r0;
            *reinterpret_cast<float4*>(&C[(size_t)gm * 128 + n0 + 4]) = r1;
        }
    }
}

// ---------------- launch -----------------------------------------------------
extern "C" void kernel_launch(void* const* d_in, const int* in_sizes, int n_in,
                              void* d_out, int out_size) {
    const float* ue   = (const float*)d_in[0];
    const float* ie   = (const float*)d_in[1];
    const int*   rows = (const int*)  d_in[2];
    const int*   cols = (const int*)  d_in[3];
    const float* vals = (const float*)d_in[4];
    const float* mask = (const float*)d_in[5];
    const float* W    = (const float*)d_in[6];
    const float* bias = (const float*)d_in[7];
    float* out = (float*)d_out;

    int nthr = N_NODES * EMB4;  // 4.8M
    k_init<<<(nthr + 255) / 256, 256>>>((const float4*)ue, (const float4*)ie);
    k_hist<<<(NNZ + 255) / 256, 256>>>(rows);
    k_scan1<<<SCAN_NB, 256>>>();
    k_scan2<<<1, 1024>>>();
    k_scan3<<<SCAN_NB, 256>>>();
    k_scatter<<<(NNZ + 255) / 256, 256>>>(rows, cols, vals);
    k_spmm<<<(N_NODES * 32 + 255) / 256, 256>>>(0);
    k_spmm<<<(N_NODES * 32 + 255) / 256, 256>>>(1);
    k_final<<<(N_NODES * 32 + 255) / 256, 256>>>((const float4*)mask, (float4*)out);

    const float* Amasked = out + (size_t)N_NODES * EMB;
    float* Cpred = out + (size_t)N_NODES * EMB + (size_t)N_USERS * EMB;
    k_gemm<<<(N_USERS + 63) / 64, 256>>>(Amasked, W, bias, Cpred, N_USERS);
}

// round 4
// speedup vs baseline: 1.2973x; 1.0756x over previous
#include <cuda_runtime.h>
#include <cuda_bf16.h>

#define N_USERS 100000
#define N_ITEMS 50000
#define N_NODES 150000
#define EMB     128
#define EMB4    32
#define NNZ     2400000
#define ALPHA   0.25f
#define SCAN_NB ((N_NODES + 255) / 256)   // 587

// ---------------- device scratch (static, no runtime allocation) ------------
// NOTE: g_cnt relies on a zero-on-entry invariant: zero-initialized at module
// load, and k_scan1 re-zeroes each slot after reading it. Every kernel_launch
// call therefore sees zeros without an explicit clearing pass.
__device__ __align__(16) __nv_bfloat16  g_embh[3][(size_t)N_NODES * EMB]; // bf16 layers 0..2
__device__ int   g_cnt[N_NODES];
__device__ int   g_off[N_NODES + 1];
__device__ int   g_fill[N_NODES];
__device__ int   g_bsum[SCAN_NB];
__device__ int   g_bscan[SCAN_NB];
__device__ uint2 g_edge[NNZ];             // (col, float-bits of val)

// ---------------- helpers ----------------------------------------------------
__device__ __forceinline__ void fma_bf16x4(uint2 u, float v, float4& acc) {
    __nv_bfloat162 b0 = *reinterpret_cast<const __nv_bfloat162*>(&u.x);
    __nv_bfloat162 b1 = *reinterpret_cast<const __nv_bfloat162*>(&u.y);
    float2 f0 = __bfloat1622float2(b0);
    float2 f1 = __bfloat1622float2(b1);
    acc.x = fmaf(v, f0.x, acc.x); acc.y = fmaf(v, f0.y, acc.y);
    acc.z = fmaf(v, f1.x, acc.z); acc.w = fmaf(v, f1.y, acc.w);
}

__device__ __forceinline__ float4 bf16x4_to_f4(uint2 u) {
    __nv_bfloat162 b0 = *reinterpret_cast<const __nv_bfloat162*>(&u.x);
    __nv_bfloat162 b1 = *reinterpret_cast<const __nv_bfloat162*>(&u.y);
    float2 f0 = __bfloat1622float2(b0);
    float2 f1 = __bfloat1622float2(b1);
    return make_float4(f0.x, f0.y, f1.x, f1.y);
}

__device__ __forceinline__ uint2 pack_bf16x4(float4 a) {
    uint2 r;
    __nv_bfloat162 h0 = __floats2bfloat162_rn(a.x, a.y);
    __nv_bfloat162 h1 = __floats2bfloat162_rn(a.z, a.w);
    r.x = *reinterpret_cast<const unsigned*>(&h0);
    r.y = *reinterpret_cast<const unsigned*>(&h1);
    return r;
}

// f32x2 packed math (sm_103a): 2 fp32 FMAs per instruction, exact fp32.
__device__ __forceinline__ unsigned long long pk2(float v) {
    unsigned long long r;
    asm("mov.b64 %0, {%1, %1};" : "=l"(r) : "f"(v));
    return r;
}
__device__ __forceinline__ void ffma2(unsigned long long& d,
                                      unsigned long long a, unsigned long long b) {
    asm("fma.rn.f32x2 %0, %1, %2, %0;" : "+l"(d) : "l"(a), "l"(b));
}
__device__ __forceinline__ float2 upk2(unsigned long long v) {
    float2 f;
    asm("mov.b64 {%0, %1}, %2;" : "=f"(f.x), "=f"(f.y) : "l"(v));
    return f;
}

// ---------------- init: bf16 layer-0 + fused edge histogram -----------------
__global__ void k_init(const float4* __restrict__ ue, const float4* __restrict__ ie,
                       const int* __restrict__ rows) {
    int i = blockIdx.x * blockDim.x + threadIdx.x;
    if (i < NNZ) atomicAdd(&g_cnt[rows[i]], 1);   // g_cnt is zero on entry (invariant)
    if (i >= N_NODES * EMB4) return;
    int node = i >> 5;
    float4 v = (node < N_USERS) ? ue[i] : ie[i - N_USERS * EMB4];
    reinterpret_cast<uint2*>(g_embh[0])[i] = pack_bf16x4(v);
}

// ---------------- CSR build: scan -> scatter ---------------------------------
__global__ void k_scan1() {
    __shared__ int s[256];
    int tid = threadIdx.x;
    int gid = blockIdx.x * 256 + tid;
    int v = (gid < N_NODES) ? g_cnt[gid] : 0;
    if (gid < N_NODES) g_cnt[gid] = 0;            // restore zero invariant
    s[tid] = v;
    __syncthreads();
#pragma unroll
    for (int d = 1; d < 256; d <<= 1) {
        int t = (tid >= d) ? s[tid - d] : 0;
        __syncthreads();
        if (tid >= d) s[tid] += t;
        __syncthreads();
    }
    if (gid < N_NODES) g_off[gid] = s[tid] - v;   // block-local exclusive
    if (tid == 255) g_bsum[blockIdx.x] = s[255];
}

__global__ void k_scan2() {
    __shared__ int s[1024];
    int tid = threadIdx.x;
    int v = (tid < SCAN_NB) ? g_bsum[tid] : 0;
    s[tid] = v;
    __syncthreads();
    for (int d = 1; d < 1024; d <<= 1) {
        int t = (tid >= d) ? s[tid - d] : 0;
        __syncthreads();
        if (tid >= d) s[tid] += t;
        __syncthreads();
    }
    if (tid < SCAN_NB) g_bscan[tid] = s[tid] - v; // exclusive block offsets
}

__global__ void k_scan3() {
    int gid = blockIdx.x * 256 + threadIdx.x;
    if (gid < N_NODES) {
        int o = g_off[gid] + g_bscan[blockIdx.x];
        g_off[gid]  = o;
        g_fill[gid] = o;
    }
    if (gid == 0) g_off[N_NODES] = NNZ;
}

__global__ void k_scatter(const int* __restrict__ rows, const int* __restrict__ cols,
                          const float* __restrict__ vals) {
    int e = blockIdx.x * blockDim.x + threadIdx.x;
    if (e >= NNZ) return;
    int p = atomicAdd(&g_fill[rows[e]], 1);
    g_edge[p] = make_uint2((unsigned)cols[e], __float_as_uint(vals[e]));
}

// ---------------- SpMM (layers 0->1, 1->2): bf16 gather, fp32 accumulate ----
__global__ void __launch_bounds__(256) k_spmm(int layer) {
    int gw   = (blockIdx.x * 256 + threadIdx.x) >> 5;
    int lane = threadIdx.x & 31;
    if (gw >= N_NODES) return;
    const uint2* __restrict__ src = reinterpret_cast<const uint2*>(g_embh[layer]);
    int beg = g_off[gw], end = g_off[gw + 1];
    float4 acc = make_float4(0.f, 0.f, 0.f, 0.f);
    int e = beg;
    for (; e + 4 <= end; e += 4) {
        uint2 e0 = __ldg(&g_edge[e]);
        uint2 e1 = __ldg(&g_edge[e + 1]);
        uint2 e2 = __ldg(&g_edge[e + 2]);
        uint2 e3 = __ldg(&g_edge[e + 3]);
        uint2 x0 = src[(size_t)e0.x * EMB4 + lane];
        uint2 x1 = src[(size_t)e1.x * EMB4 + lane];
        uint2 x2 = src[(size_t)e2.x * EMB4 + lane];
        uint2 x3 = src[(size_t)e3.x * EMB4 + lane];
        fma_bf16x4(x0, __uint_as_float(e0.y), acc);
        fma_bf16x4(x1, __uint_as_float(e1.y), acc);
        fma_bf16x4(x2, __uint_as_float(e2.y), acc);
        fma_bf16x4(x3, __uint_as_float(e3.y), acc);
    }
    for (; e < end; e++) {
        uint2 ed = __ldg(&g_edge[e]);
        uint2 x  = src[(size_t)ed.x * EMB4 + lane];
        fma_bf16x4(x, __uint_as_float(ed.y), acc);
    }
    reinterpret_cast<uint2*>(g_embh[layer + 1])[(size_t)gw * EMB4 + lane] = pack_bf16x4(acc);
}

// ---------------- final: SpMM layer 2->3 fused with combine + outputs -------
// out layout (floats): [user_final 100000x128][item_final 50000x128]
//                      [masked_user 100000x128][predicted 100000x128][mask 100000x128]
// user_final + item_final are contiguous => all nodes write out[ri].
#define O2_4 ((size_t)N_NODES * EMB4)                       // masked_user
#define O3_4 (O2_4 + (size_t)N_USERS * EMB4)                // predicted
#define O4_4 (O3_4 + (size_t)N_USERS * EMB4)                // mask

__global__ void __launch_bounds__(256) k_final(const float4* __restrict__ ue,
                                               const float4* __restrict__ ie,
                                               const float4* __restrict__ mask,
                                               float4* __restrict__ out) {
    int gw   = (blockIdx.x * 256 + threadIdx.x) >> 5;
    int lane = threadIdx.x & 31;
    if (gw >= N_NODES) return;
    const uint2* __restrict__ src = reinterpret_cast<const uint2*>(g_embh[2]);
    int beg = g_off[gw], end = g_off[gw + 1];
    float4 acc = make_float4(0.f, 0.f, 0.f, 0.f);
    int e = beg;
    for (; e + 4 <= end; e += 4) {
        uint2 e0 = __ldg(&g_edge[e]);
        uint2 e1 = __ldg(&g_edge[e + 1]);
        uint2 e2 = __ldg(&g_edge[e + 2]);
        uint2 e3 = __ldg(&g_edge[e + 3]);
        uint2 x0 = src[(size_t)e0.x * EMB4 + lane];
        uint2 x1 = src[(size_t)e1.x * EMB4 + lane];
        uint2 x2 = src[(size_t)e2.x * EMB4 + lane];
        uint2 x3 = src[(size_t)e3.x * EMB4 + lane];
        fma_bf16x4(x0, __uint_as_float(e0.y), acc);
        fma_bf16x4(x1, __uint_as_float(e1.y), acc);
        fma_bf16x4(x2, __uint_as_float(e2.y), acc);
        fma_bf16x4(x3, __uint_as_float(e3.y), acc);
    }
    for (; e < end; e++) {
        uint2 ed = __ldg(&g_edge[e]);
        uint2 x  = src[(size_t)ed.x * EMB4 + lane];
        fma_bf16x4(x, __uint_as_float(ed.y), acc);
    }
    size_t ri = (size_t)gw * EMB4 + lane;
    // layer 0 exact from inputs; layers 1,2 from bf16 tables
    float4 a = (gw < N_USERS) ? ue[ri] : ie[ri - (size_t)N_USERS * EMB4];
    float4 b = bf16x4_to_f4(reinterpret_cast<const uint2*>(g_embh[1])[ri]);
    float4 c = bf16x4_to_f4(reinterpret_cast<const uint2*>(g_embh[2])[ri]);
    float4 comb;
    comb.x = ALPHA * (a.x + b.x + c.x + acc.x);
    comb.y = ALPHA * (a.y + b.y + c.y + acc.y);
    comb.z = ALPHA * (a.z + b.z + c.z + acc.z);
    comb.w = ALPHA * (a.w + b.w + c.w + acc.w);
    out[ri] = comb;                    // user_final / item_final (contiguous)
    if (gw < N_USERS) {
        float4 m = mask[ri];
        float4 mu = make_float4(comb.x * m.x, comb.y * m.y, comb.z * m.z, comb.w * m.w);
        out[O2_4 + ri] = mu;
        out[O4_4 + ri] = m;
    }
}

// ---------------- GEMM: predicted = relu(masked @ W + b), f32x2 path --------
__global__ void __launch_bounds__(256) k_gemm(const float* __restrict__ A,
                                              const float* __restrict__ W,
                                              const float* __restrict__ bias,
                                              float* __restrict__ C, int M) {
    __shared__ float As[32][68];    // [k][m], padded
    __shared__ float Ws[32][128];   // [k][n]
    int tid = threadIdx.x;
    int m_base = blockIdx.x * 64;
    int tx = tid & 15;      // n group: 8 cols each
    int ty = tid >> 4;      // m group: 4 rows each
    int n0 = tx * 8;
    int m0 = ty * 4;
    unsigned long long acc2[4][4];   // [m][n-pair], each holds 2 fp32
#pragma unroll
    for (int i = 0; i < 4; i++)
#pragma unroll
        for (int j = 0; j < 4; j++) acc2[i][j] = 0ull;

    for (int kk = 0; kk < 128; kk += 32) {
        int am = tid >> 3;              // 0..31
        int ak = (tid & 7) * 4;         // 0..28
#pragma unroll
        for (int p = 0; p < 2; p++) {
            int m  = am + p * 32;
            int gm = m_base + m;
            float4 v = (gm < M) ? *reinterpret_cast<const float4*>(&A[(size_t)gm * 128 + kk + ak])
                                : make_float4(0.f, 0.f, 0.f, 0.f);
            As[ak + 0][m] = v.x; As[ak + 1][m] = v.y;
            As[ak + 2][m] = v.z; As[ak + 3][m] = v.w;
        }
#pragma unroll
        for (int p = 0; p < 4; p++) {
            int idx = (tid + p * 256) * 4;
            int k = idx >> 7, n = idx & 127;
            *reinterpret_cast<float4*>(&Ws[k][n]) =
                *reinterpret_cast<const float4*>(&W[(size_t)(kk + k) * 128 + n]);
        }
        __syncthreads();
#pragma unroll
        for (int k = 0; k < 32; k++) {
            float4 a4 = *reinterpret_cast<float4*>(&As[k][m0]);
            ulonglong2 w01 = *reinterpret_cast<ulonglong2*>(&Ws[k][n0]);
            ulonglong2 w23 = *reinterpret_cast<ulonglong2*>(&Ws[k][n0 + 4]);
            unsigned long long wv[4] = {w01.x, w01.y, w23.x, w23.y};
            unsigned long long av[4] = {pk2(a4.x), pk2(a4.y), pk2(a4.z), pk2(a4.w)};
#pragma unroll
            for (int i = 0; i < 4; i++)
#pragma unroll
                for (int j = 0; j < 4; j++)
                    ffma2(acc2[i][j], av[i], wv[j]);
        }
        __syncthreads();
    }
    float bv[8];
#pragma unroll
    for (int j = 0; j < 8; j++) bv[j] = bias[n0 + j];
#pragma unroll
    for (int i = 0; i < 4; i++) {
        int gm = m_base + m0 + i;
        if (gm < M) {
            float2 p0 = upk2(acc2[i][0]);
            float2 p1 = upk2(acc2[i][1]);
            float2 p2 = upk2(acc2[i][2]);
            float2 p3 = upk2(acc2[i][3]);
            float4 r0, r1;
            r0.x = fmaxf(p0.x + bv[0], 0.f); r0.y = fmaxf(p0.y + bv[1], 0.f);
            r0.z = fmaxf(p1.x + bv[2], 0.f); r0.w = fmaxf(p1.y + bv[3], 0.f);
            r1.x = fmaxf(p2.x + bv[4], 0.f); r1.y = fmaxf(p2.y + bv[5], 0.f);
            r1.z = fmaxf(p3.x + bv[6], 0.f); r1.w = fmaxf(p3.y + bv[7], 0.f);
            *reinterpret_cast<float4*>(&C[(size_t)gm * 128 + n0])     = r0;
            *reinterpret_cast<float4*>(&C[(size_t)gm * 128 + n0 + 4]) = r1;
        }
    }
}

// ---------------- launch -----------------------------------------------------
extern "C" void kernel_launch(void* const* d_in, const int* in_sizes, int n_in,
                              void* d_out, int out_size) {
    const float* ue   = (const float*)d_in[0];
    const float* ie   = (const float*)d_in[1];
    const int*   rows = (const int*)  d_in[2];
    const int*   cols = (const int*)  d_in[3];
    const float* vals = (const float*)d_in[4];
    const float* mask = (const float*)d_in[5];
    const float* W    = (const float*)d_in[6];
    const float* bias = (const float*)d_in[7];
    float* out = (float*)d_out;

    int nthr = N_NODES * EMB4;  // 4.8M
    k_init<<<(nthr + 255) / 256, 256>>>((const float4*)ue, (const float4*)ie, rows);
    k_scan1<<<SCAN_NB, 256>>>();
    k_scan2<<<1, 1024>>>();
    k_scan3<<<SCAN_NB, 256>>>();
    k_scatter<<<(NNZ + 255) / 256, 256>>>(rows, cols, vals);
    k_spmm<<<(N_NODES * 32 + 255) / 256, 256>>>(0);
    k_spmm<<<(N_NODES * 32 + 255) / 256, 256>>>(1);
    k_final<<<(N_NODES * 32 + 255) / 256, 256>>>((const float4*)ue, (const float4*)ie,
                                                 (const float4*)mask, (float4*)out);

    const float* Amasked = out + (size_t)N_NODES * EMB;
    float* Cpred = out + (size_t)N_NODES * EMB + (size_t)N_USERS * EMB;
    k_gemm<<<(N_USERS + 63) / 64, 256>>>(Amasked, W, bias, Cpred, N_USERS);
}

// round 5
// speedup vs baseline: 1.4930x; 1.1508x over previous
#include <cuda_runtime.h>
#include <cuda_bf16.h>

#define N_USERS 100000
#define N_ITEMS 50000
#define N_NODES 150000
#define EMB     128
#define EMB4    32
#define NNZ     2400000
#define ALPHA   0.25f
#define SCAN_NB ((N_NODES + 255) / 256)

// ---------------- device scratch (static, no runtime allocation) ------------
// g_cnt zero-on-entry invariant: zeroed at load; k_scan re-zeroes after read.
// g_blkdesc reset each call by k_init (ordered before k_scan on the stream).
__device__ __align__(16) __nv_bfloat16  g_embh[3][(size_t)N_NODES * EMB]; // bf16 layers 0..2
__device__ int   g_cnt[N_NODES];
__device__ int   g_off[N_NODES + 1];
__device__ int   g_fill[N_NODES];
__device__ unsigned long long g_blkdesc[SCAN_NB]; // hi32: 0 inval,1 agg,2 incl; lo32 sum
__device__ uint2 g_edge[NNZ];                     // (col, float-bits of val)

// ---------------- helpers ----------------------------------------------------
__device__ __forceinline__ void fma_bf16x4(uint2 u, float v, float4& acc) {
    __nv_bfloat162 b0 = *reinterpret_cast<const __nv_bfloat162*>(&u.x);
    __nv_bfloat162 b1 = *reinterpret_cast<const __nv_bfloat162*>(&u.y);
    float2 f0 = __bfloat1622float2(b0);
    float2 f1 = __bfloat1622float2(b1);
    acc.x = fmaf(v, f0.x, acc.x); acc.y = fmaf(v, f0.y, acc.y);
    acc.z = fmaf(v, f1.x, acc.z); acc.w = fmaf(v, f1.y, acc.w);
}

__device__ __forceinline__ float4 bf16x4_to_f4(uint2 u) {
    __nv_bfloat162 b0 = *reinterpret_cast<const __nv_bfloat162*>(&u.x);
    __nv_bfloat162 b1 = *reinterpret_cast<const __nv_bfloat162*>(&u.y);
    float2 f0 = __bfloat1622float2(b0);
    float2 f1 = __bfloat1622float2(b1);
    return make_float4(f0.x, f0.y, f1.x, f1.y);
}

__device__ __forceinline__ uint2 pack_bf16x4(float4 a) {
    uint2 r;
    __nv_bfloat162 h0 = __floats2bfloat162_rn(a.x, a.y);
    __nv_bfloat162 h1 = __floats2bfloat162_rn(a.z, a.w);
    r.x = *reinterpret_cast<const unsigned*>(&h0);
    r.y = *reinterpret_cast<const unsigned*>(&h1);
    return r;
}

// f32x2 packed math (sm_103a): 2 fp32 FMAs per instruction, exact fp32.
__device__ __forceinline__ unsigned long long pk2(float v) {
    unsigned long long r;
    asm("mov.b64 %0, {%1, %1};" : "=l"(r) : "f"(v));
    return r;
}
__device__ __forceinline__ void ffma2(unsigned long long& d,
                                      unsigned long long a, unsigned long long b) {
    asm("fma.rn.f32x2 %0, %1, %2, %0;" : "+l"(d) : "l"(a), "l"(b));
}
__device__ __forceinline__ float2 upk2(unsigned long long v) {
    float2 f;
    asm("mov.b64 {%0, %1}, %2;" : "=f"(f.x), "=f"(f.y) : "l"(v));
    return f;
}

// ---------------- init: bf16 layer-0 + fused edge histogram + scan reset ----
__global__ void k_init(const float4* __restrict__ ue, const float4* __restrict__ ie,
                       const int* __restrict__ rows) {
    int i = blockIdx.x * blockDim.x + threadIdx.x;
    if (i < SCAN_NB) g_blkdesc[i] = 0ull;
    if (i < NNZ) atomicAdd(&g_cnt[rows[i]], 1);   // g_cnt zero on entry (invariant)
    if (i >= N_NODES * EMB4) return;
    int node = i >> 5;
    float4 v = (node < N_USERS) ? ue[i] : ie[i - N_USERS * EMB4];
    reinterpret_cast<uint2*>(g_embh[0])[i] = pack_bf16x4(v);
}

// ---------------- single-pass scan (decoupled lookback) ----------------------
__global__ void __launch_bounds__(256) k_scan() {
    __shared__ int s[256];
    __shared__ int s_base;
    int tid = threadIdx.x, bid = blockIdx.x;
    int gid = bid * 256 + tid;
    int v = (gid < N_NODES) ? g_cnt[gid] : 0;
    if (gid < N_NODES) g_cnt[gid] = 0;            // restore zero invariant
    s[tid] = v;
    __syncthreads();
#pragma unroll
    for (int d = 1; d < 256; d <<= 1) {
        int t = (tid >= d) ? s[tid - d] : 0;
        __syncthreads();
        if (tid >= d) s[tid] += t;
        __syncthreads();
    }
    int incl = s[tid];
    int agg  = s[255];
    if (tid == 0) {
        unsigned long long w = ((bid == 0 ? 2ULL : 1ULL) << 32) | (unsigned)agg;
        atomicExch(&g_blkdesc[bid], w);
        if (bid == 0) s_base = 0;
    }
    if (bid > 0 && tid < 32) {
        int lane = tid;
        int exc = 0;
        int look = bid - 1;
        while (true) {
            int idx = look - lane;
            unsigned long long w;
            if (idx >= 0) {
                do { w = *(volatile unsigned long long*)&g_blkdesc[idx]; }
                while ((unsigned)(w >> 32) == 0u);
            } else {
                w = (2ULL << 32);
            }
            unsigned st = (unsigned)(w >> 32);
            int val = (int)(unsigned)w;
            unsigned bal = __ballot_sync(0xffffffffu, st == 2u);
            int first = __ffs(bal) - 1;             // closest inclusive (if any)
            int contrib = bal ? ((lane <= first) ? val : 0) : val;
#pragma unroll
            for (int o = 16; o; o >>= 1) contrib += __shfl_down_sync(0xffffffffu, contrib, o);
            contrib = __shfl_sync(0xffffffffu, contrib, 0);
            exc += contrib;
            if (bal) break;
            look -= 32;
        }
        if (lane == 0) {
            atomicExch(&g_blkdesc[bid], (2ULL << 32) | (unsigned)(exc + agg));
            s_base = exc;
        }
    }
    __syncthreads();
    int base = s_base;
    if (gid < N_NODES) {
        int o = base + incl - v;
        g_off[gid]  = o;
        g_fill[gid] = o;
    }
    if (gid == 0) g_off[N_NODES] = NNZ;
}

__global__ void k_scatter(const int* __restrict__ rows, const int* __restrict__ cols,
                          const float* __restrict__ vals) {
    int e = blockIdx.x * blockDim.x + threadIdx.x;
    if (e >= NNZ) return;
    int p = atomicAdd(&g_fill[rows[e]], 1);
    g_edge[p] = make_uint2((unsigned)cols[e], __float_as_uint(vals[e]));
}

// ---------------- SpMM (layers 0->1, 1->2): bf16 gather, fp32 accumulate ----
__global__ void __launch_bounds__(256) k_spmm(int layer) {
    int gw   = (blockIdx.x * 256 + threadIdx.x) >> 5;
    int lane = threadIdx.x & 31;
    if (gw >= N_NODES) return;
    const uint2* __restrict__ src = reinterpret_cast<const uint2*>(g_embh[layer]);
    int beg = g_off[gw], end = g_off[gw + 1];
    float4 acc = make_float4(0.f, 0.f, 0.f, 0.f);
    int e = beg;
    for (; e + 8 <= end; e += 8) {
        uint2 ed[8], x[8];
#pragma unroll
        for (int u = 0; u < 8; u++) ed[u] = __ldg(&g_edge[e + u]);
#pragma unroll
        for (int u = 0; u < 8; u++) x[u] = src[(size_t)ed[u].x * EMB4 + lane];
#pragma unroll
        for (int u = 0; u < 8; u++) fma_bf16x4(x[u], __uint_as_float(ed[u].y), acc);
    }
    for (; e + 2 <= end; e += 2) {
        uint2 e0 = __ldg(&g_edge[e]);
        uint2 e1 = __ldg(&g_edge[e + 1]);
        uint2 x0 = src[(size_t)e0.x * EMB4 + lane];
        uint2 x1 = src[(size_t)e1.x * EMB4 + lane];
        fma_bf16x4(x0, __uint_as_float(e0.y), acc);
        fma_bf16x4(x1, __uint_as_float(e1.y), acc);
    }
    if (e < end) {
        uint2 ed = __ldg(&g_edge[e]);
        uint2 x  = src[(size_t)ed.x * EMB4 + lane];
        fma_bf16x4(x, __uint_as_float(ed.y), acc);
    }
    reinterpret_cast<uint2*>(g_embh[layer + 1])[(size_t)gw * EMB4 + lane] = pack_bf16x4(acc);
}

// ---------------- final: SpMM layer 2->3 fused with combine + outputs -------
#define O2_4 ((size_t)N_NODES * EMB4)                       // masked_user
#define O3_4 (O2_4 + (size_t)N_USERS * EMB4)                // predicted
#define O4_4 (O3_4 + (size_t)N_USERS * EMB4)                // mask

__global__ void __launch_bounds__(256) k_final(const float4* __restrict__ ue,
                                               const float4* __restrict__ ie,
                                               const float4* __restrict__ mask,
                                               float4* __restrict__ out) {
    int gw   = (blockIdx.x * 256 + threadIdx.x) >> 5;
    int lane = threadIdx.x & 31;
    if (gw >= N_NODES) return;
    const uint2* __restrict__ src = reinterpret_cast<const uint2*>(g_embh[2]);
    int beg = g_off[gw], end = g_off[gw + 1];
    float4 acc = make_float4(0.f, 0.f, 0.f, 0.f);
    int e = beg;
    for (; e + 8 <= end; e += 8) {
        uint2 ed[8], x[8];
#pragma unroll
        for (int u = 0; u < 8; u++) ed[u] = __ldg(&g_edge[e + u]);
#pragma unroll
        for (int u = 0; u < 8; u++) x[u] = src[(size_t)ed[u].x * EMB4 + lane];
#pragma unroll
        for (int u = 0; u < 8; u++) fma_bf16x4(x[u], __uint_as_float(ed[u].y), acc);
    }
    for (; e + 2 <= end; e += 2) {
        uint2 e0 = __ldg(&g_edge[e]);
        uint2 e1 = __ldg(&g_edge[e + 1]);
        uint2 x0 = src[(size_t)e0.x * EMB4 + lane];
        uint2 x1 = src[(size_t)e1.x * EMB4 + lane];
        fma_bf16x4(x0, __uint_as_float(e0.y), acc);
        fma_bf16x4(x1, __uint_as_float(e1.y), acc);
    }
    if (e < end) {
        uint2 ed = __ldg(&g_edge[e]);
        uint2 x  = src[(size_t)ed.x * EMB4 + lane];
        fma_bf16x4(x, __uint_as_float(ed.y), acc);
    }
    size_t ri = (size_t)gw * EMB4 + lane;
    float4 a = (gw < N_USERS) ? ue[ri] : ie[ri - (size_t)N_USERS * EMB4];
    float4 b = bf16x4_to_f4(reinterpret_cast<const uint2*>(g_embh[1])[ri]);
    float4 c = bf16x4_to_f4(reinterpret_cast<const uint2*>(g_embh[2])[ri]);
    float4 comb;
    comb.x = ALPHA * (a.x + b.x + c.x + acc.x);
    comb.y = ALPHA * (a.y + b.y + c.y + acc.y);
    comb.z = ALPHA * (a.z + b.z + c.z + acc.z);
    comb.w = ALPHA * (a.w + b.w + c.w + acc.w);
    out[ri] = comb;                    // user_final / item_final (contiguous)
    if (gw < N_USERS) {
        float4 m = mask[ri];
        float4 mu = make_float4(comb.x * m.x, comb.y * m.y, comb.z * m.z, comb.w * m.w);
        out[O2_4 + ri] = mu;
        out[O4_4 + ri] = m;
    }
}

// ---------------- GEMM 128x128x16: predicted = relu(masked @ W + b) ---------
// Thread tile 8m x 8n; W smem granule-major with odd pad (2-way conflicts max);
// thread owns W granules {tx, tx+16} -> output cols [4tx,4tx+4) and [64+4tx,..).
__global__ void __launch_bounds__(256) k_gemm(const float* __restrict__ A,
                                              const float* __restrict__ W,
                                              const float* __restrict__ bias,
                                              float* __restrict__ C, int M) {
    __shared__ float  As[16][132];     // [k][m]
    __shared__ float4 Ws4[32 * 17];    // [granule][k] (+1 pad slot per granule)
    int tid = threadIdx.x;
    int m_base = blockIdx.x * 128;
    int tx = tid & 15;        // n granule index
    int ty = tid >> 4;        // m group: 8 rows each
    int m0 = ty * 8;
    unsigned long long acc2[8][4];
#pragma unroll
    for (int i = 0; i < 8; i++)
#pragma unroll
        for (int j = 0; j < 4; j++) acc2[i][j] = 0ull;

    for (int kk = 0; kk < 128; kk += 16) {
        // A tile: 128 rows x 16 k, transposed into As[k][m]
#pragma unroll
        for (int p = 0; p < 2; p++) {
            int idx = tid + p * 256;
            int row = idx >> 2;
            int c4  = (idx & 3) * 4;
            int gm  = m_base + row;
            float4 v = (gm < M) ? *reinterpret_cast<const float4*>(&A[(size_t)gm * 128 + kk + c4])
                                : make_float4(0.f, 0.f, 0.f, 0.f);
            As[c4 + 0][row] = v.x; As[c4 + 1][row] = v.y;
            As[c4 + 2][row] = v.z; As[c4 + 3][row] = v.w;
        }
        // W tile: 16 k x 128 n, granule-major
#pragma unroll
        for (int p = 0; p < 2; p++) {
            int idx = tid + p * 256;
            int k  = idx >> 5;
            int n4 = idx & 31;
            Ws4[n4 * 17 + k] =
                *reinterpret_cast<const float4*>(&W[(size_t)(kk + k) * 128 + n4 * 4]);
        }
        __syncthreads();
#pragma unroll
        for (int k = 0; k < 16; k++) {
            float4 a0 = *reinterpret_cast<float4*>(&As[k][m0]);
            float4 a1 = *reinterpret_cast<float4*>(&As[k][m0 + 4]);
            ulonglong2 wA = *reinterpret_cast<ulonglong2*>(&Ws4[tx * 17 + k]);
            ulonglong2 wB = *reinterpret_cast<ulonglong2*>(&Ws4[(tx + 16) * 17 + k]);
            unsigned long long wv[4] = {wA.x, wA.y, wB.x, wB.y};
            unsigned long long av[8] = {pk2(a0.x), pk2(a0.y), pk2(a0.z), pk2(a0.w),
                                        pk2(a1.x), pk2(a1.y), pk2(a1.z), pk2(a1.w)};
#pragma unroll
            for (int i = 0; i < 8; i++)
#pragma unroll
                for (int j = 0; j < 4; j++)
                    ffma2(acc2[i][j], av[i], wv[j]);
        }
        __syncthreads();
    }
    int nA = tx * 4, nB = 64 + tx * 4;
    float bA[4], bB[4];
#pragma unroll
    for (int j = 0; j < 4; j++) { bA[j] = bias[nA + j]; bB[j] = bias[nB + j]; }
#pragma unroll
    for (int i = 0; i < 8; i++) {
        int gm = m_base + m0 + i;
        if (gm < M) {
            float2 p0 = upk2(acc2[i][0]);
            float2 p1 = upk2(acc2[i][1]);
            float2 p2 = upk2(acc2[i][2]);
            float2 p3 = upk2(acc2[i][3]);
            float4 r0, r1;
            r0.x = fmaxf(p0.x + bA[0], 0.f); r0.y = fmaxf(p0.y + bA[1], 0.f);
            r0.z = fmaxf(p1.x + bA[2], 0.f); r0.w = fmaxf(p1.y + bA[3], 0.f);
            r1.x = fmaxf(p2.x + bB[0], 0.f); r1.y = fmaxf(p2.y + bB[1], 0.f);
            r1.z = fmaxf(p3.x + bB[2], 0.f); r1.w = fmaxf(p3.y + bB[3], 0.f);
            *reinterpret_cast<float4*>(&C[(size_t)gm * 128 + nA]) = r0;
            *reinterpret_cast<float4*>(&C[(size_t)gm * 128 + nB]) = r1;
        }
    }
}

// ---------------- launch -----------------------------------------------------
extern "C" void kernel_launch(void* const* d_in, const int* in_sizes, int n_in,
                              void* d_out, int out_size) {
    const float* ue   = (const float*)d_in[0];
    const float* ie   = (const float*)d_in[1];
    const int*   rows = (const int*)  d_in[2];
    const int*   cols = (const int*)  d_in[3];
    const float* vals = (const float*)d_in[4];
    const float* mask = (const float*)d_in[5];
    const float* W    = (const float*)d_in[6];
    const float* bias = (const float*)d_in[7];
    float* out = (float*)d_out;

    int nthr = N_NODES * EMB4;  // 4.8M
    k_init<<<(nthr + 255) / 256, 256>>>((const float4*)ue, (const float4*)ie, rows);
    k_scan<<<SCAN_NB, 256>>>();
    k_scatter<<<(NNZ + 255) / 256, 256>>>(rows, cols, vals);
    k_spmm<<<(N_NODES * 32 + 255) / 256, 256>>>(0);
    k_spmm<<<(N_NODES * 32 + 255) / 256, 256>>>(1);
    k_final<<<(N_NODES * 32 + 255) / 256, 256>>>((const float4*)ue, (const float4*)ie,
                                                 (const float4*)mask, (float4*)out);

    const float* Amasked = out + (size_t)N_NODES * EMB;
    float* Cpred = out + (size_t)N_NODES * EMB + (size_t)N_USERS * EMB;
    k_gemm<<<(N_USERS + 127) / 128, 256>>>(Amasked, W, bias, Cpred, N_USERS);
}

// round 6
// speedup vs baseline: 1.4957x; 1.0018x over previous
#include <cuda_runtime.h>
#include <cuda_bf16.h>

#define N_USERS 100000
#define N_ITEMS 50000
#define N_NODES 150000
#define EMB     128
#define EMB4    32
#define NNZ     2400000
#define ALPHA   0.25f
#define SCAN_NB ((N_NODES + 255) / 256)

// ---------------- device scratch (static, no runtime allocation) ------------
// g_cnt zero-on-entry invariant: zeroed at load; k_scan re-zeroes after read.
// g_blkdesc reset each call by k_init (ordered before k_scan on the stream).
__device__ __align__(16) __nv_bfloat16  g_embh[3][(size_t)N_NODES * EMB]; // bf16 layers 0..2
__device__ int   g_cnt[N_NODES];
__device__ int   g_off[N_NODES + 1];
__device__ int   g_fill[N_NODES];
__device__ unsigned long long g_blkdesc[SCAN_NB]; // hi32: 0 inval,1 agg,2 incl; lo32 sum
__device__ uint2 g_edge[NNZ];                     // (col, float-bits of val)

// ---------------- helpers ----------------------------------------------------
__device__ __forceinline__ void fma_bf16x4(uint2 u, float v, float4& acc) {
    __nv_bfloat162 b0 = *reinterpret_cast<const __nv_bfloat162*>(&u.x);
    __nv_bfloat162 b1 = *reinterpret_cast<const __nv_bfloat162*>(&u.y);
    float2 f0 = __bfloat1622float2(b0);
    float2 f1 = __bfloat1622float2(b1);
    acc.x = fmaf(v, f0.x, acc.x); acc.y = fmaf(v, f0.y, acc.y);
    acc.z = fmaf(v, f1.x, acc.z); acc.w = fmaf(v, f1.y, acc.w);
}

__device__ __forceinline__ float4 bf16x4_to_f4(uint2 u) {
    __nv_bfloat162 b0 = *reinterpret_cast<const __nv_bfloat162*>(&u.x);
    __nv_bfloat162 b1 = *reinterpret_cast<const __nv_bfloat162*>(&u.y);
    float2 f0 = __bfloat1622float2(b0);
    float2 f1 = __bfloat1622float2(b1);
    return make_float4(f0.x, f0.y, f1.x, f1.y);
}

__device__ __forceinline__ uint2 pack_bf16x4(float4 a) {
    uint2 r;
    __nv_bfloat162 h0 = __floats2bfloat162_rn(a.x, a.y);
    __nv_bfloat162 h1 = __floats2bfloat162_rn(a.z, a.w);
    r.x = *reinterpret_cast<const unsigned*>(&h0);
    r.y = *reinterpret_cast<const unsigned*>(&h1);
    return r;
}

// f32x2 packed math (sm_103a): 2 fp32 FMAs per instruction, exact fp32.
__device__ __forceinline__ unsigned long long pk2(float v) {
    unsigned long long r;
    asm("mov.b64 %0, {%1, %1};" : "=l"(r) : "f"(v));
    return r;
}
__device__ __forceinline__ void ffma2(unsigned long long& d,
                                      unsigned long long a, unsigned long long b) {
    asm("fma.rn.f32x2 %0, %1, %2, %0;" : "+l"(d) : "l"(a), "l"(b));
}
__device__ __forceinline__ float2 upk2(unsigned long long v) {
    float2 f;
    asm("mov.b64 {%0, %1}, %2;" : "=f"(f.x), "=f"(f.y) : "l"(v));
    return f;
}

// ---------------- init: bf16 layer-0 + fused edge histogram + scan reset ----
__global__ void k_init(const float4* __restrict__ ue, const float4* __restrict__ ie,
                       const int* __restrict__ rows) {
    int i = blockIdx.x * blockDim.x + threadIdx.x;
    if (i < SCAN_NB) g_blkdesc[i] = 0ull;
    if (i < NNZ) atomicAdd(&g_cnt[rows[i]], 1);   // g_cnt zero on entry (invariant)
    if (i >= N_NODES * EMB4) return;
    int node = i >> 5;
    float4 v = (node < N_USERS) ? ue[i] : ie[i - N_USERS * EMB4];
    reinterpret_cast<uint2*>(g_embh[0])[i] = pack_bf16x4(v);
}

// ---------------- single-pass scan (decoupled lookback) ----------------------
__global__ void __launch_bounds__(256) k_scan() {
    __shared__ int s[256];
    __shared__ int s_base;
    int tid = threadIdx.x, bid = blockIdx.x;
    int gid = bid * 256 + tid;
    int v = (gid < N_NODES) ? g_cnt[gid] : 0;
    if (gid < N_NODES) g_cnt[gid] = 0;            // restore zero invariant
    s[tid] = v;
    __syncthreads();
#pragma unroll
    for (int d = 1; d < 256; d <<= 1) {
        int t = (tid >= d) ? s[tid - d] : 0;
        __syncthreads();
        if (tid >= d) s[tid] += t;
        __syncthreads();
    }
    int incl = s[tid];
    int agg  = s[255];
    if (tid == 0) {
        unsigned long long w = ((bid == 0 ? 2ULL : 1ULL) << 32) | (unsigned)agg;
        atomicExch(&g_blkdesc[bid], w);
        if (bid == 0) s_base = 0;
    }
    if (bid > 0 && tid < 32) {
        int lane = tid;
        int exc = 0;
        int look = bid - 1;
        while (true) {
            int idx = look - lane;
            unsigned long long w;
            if (idx >= 0) {
                do { w = *(volatile unsigned long long*)&g_blkdesc[idx]; }
                while ((unsigned)(w >> 32) == 0u);
            } else {
                w = (2ULL << 32);
            }
            unsigned st = (unsigned)(w >> 32);
            int val = (int)(unsigned)w;
            unsigned bal = __ballot_sync(0xffffffffu, st == 2u);
            int first = __ffs(bal) - 1;             // closest inclusive (if any)
            int contrib = bal ? ((lane <= first) ? val : 0) : val;
#pragma unroll
            for (int o = 16; o; o >>= 1) contrib += __shfl_down_sync(0xffffffffu, contrib, o);
            contrib = __shfl_sync(0xffffffffu, contrib, 0);
            exc += contrib;
            if (bal) break;
            look -= 32;
        }
        if (lane == 0) {
            atomicExch(&g_blkdesc[bid], (2ULL << 32) | (unsigned)(exc + agg));
            s_base = exc;
        }
    }
    __syncthreads();
    int base = s_base;
    if (gid < N_NODES) {
        int o = base + incl - v;
        g_off[gid]  = o;
        g_fill[gid] = o;
    }
    if (gid == 0) g_off[N_NODES] = NNZ;
}

__global__ void k_scatter(const int* __restrict__ rows, const int* __restrict__ cols,
                          const float* __restrict__ vals) {
    int e = blockIdx.x * blockDim.x + threadIdx.x;
    if (e >= NNZ) return;
    int p = atomicAdd(&g_fill[rows[e]], 1);
    g_edge[p] = make_uint2((unsigned)cols[e], __float_as_uint(vals[e]));
}

// ---------------- SpMM (layers 0->1, 1->2): bf16 gather, fp32 accumulate ----
__global__ void __launch_bounds__(256) k_spmm(int layer) {
    int gw   = (blockIdx.x * 256 + threadIdx.x) >> 5;
    int lane = threadIdx.x & 31;
    if (gw >= N_NODES) return;
    const uint2* __restrict__ src = reinterpret_cast<const uint2*>(g_embh[layer]);
    int beg = g_off[gw], end = g_off[gw + 1];
    float4 acc = make_float4(0.f, 0.f, 0.f, 0.f);
    int e = beg;
    for (; e + 8 <= end; e += 8) {
        uint2 ed[8], x[8];
#pragma unroll
        for (int u = 0; u < 8; u++) ed[u] = __ldg(&g_edge[e + u]);
#pragma unroll
        for (int u = 0; u < 8; u++) x[u] = src[(size_t)ed[u].x * EMB4 + lane];
#pragma unroll
        for (int u = 0; u < 8; u++) fma_bf16x4(x[u], __uint_as_float(ed[u].y), acc);
    }
    for (; e + 2 <= end; e += 2) {
        uint2 e0 = __ldg(&g_edge[e]);
        uint2 e1 = __ldg(&g_edge[e + 1]);
        uint2 x0 = src[(size_t)e0.x * EMB4 + lane];
        uint2 x1 = src[(size_t)e1.x * EMB4 + lane];
        fma_bf16x4(x0, __uint_as_float(e0.y), acc);
        fma_bf16x4(x1, __uint_as_float(e1.y), acc);
    }
    if (e < end) {
        uint2 ed = __ldg(&g_edge[e]);
        uint2 x  = src[(size_t)ed.x * EMB4 + lane];
        fma_bf16x4(x, __uint_as_float(ed.y), acc);
    }
    reinterpret_cast<uint2*>(g_embh[layer + 1])[(size_t)gw * EMB4 + lane] = pack_bf16x4(acc);
}

// ---------------- final: SpMM layer 2->3 fused with combine + outputs -------
#define O2_4 ((size_t)N_NODES * EMB4)                       // masked_user
#define O3_4 (O2_4 + (size_t)N_USERS * EMB4)                // predicted
#define O4_4 (O3_4 + (size_t)N_USERS * EMB4)                // mask

__global__ void __launch_bounds__(256) k_final(const float4* __restrict__ ue,
                                               const float4* __restrict__ ie,
                                               const float4* __restrict__ mask,
                                               float4* __restrict__ out) {
    int gw   = (blockIdx.x * 256 + threadIdx.x) >> 5;
    int lane = threadIdx.x & 31;
    if (gw >= N_NODES) return;
    const uint2* __restrict__ src = reinterpret_cast<const uint2*>(g_embh[2]);
    int beg = g_off[gw], end = g_off[gw + 1];
    float4 acc = make_float4(0.f, 0.f, 0.f, 0.f);
    int e = beg;
    for (; e + 8 <= end; e += 8) {
        uint2 ed[8], x[8];
#pragma unroll
        for (int u = 0; u < 8; u++) ed[u] = __ldg(&g_edge[e + u]);
#pragma unroll
        for (int u = 0; u < 8; u++) x[u] = src[(size_t)ed[u].x * EMB4 + lane];
#pragma unroll
        for (int u = 0; u < 8; u++) fma_bf16x4(x[u], __uint_as_float(ed[u].y), acc);
    }
    for (; e + 2 <= end; e += 2) {
        uint2 e0 = __ldg(&g_edge[e]);
        uint2 e1 = __ldg(&g_edge[e + 1]);
        uint2 x0 = src[(size_t)e0.x * EMB4 + lane];
        uint2 x1 = src[(size_t)e1.x * EMB4 + lane];
        fma_bf16x4(x0, __uint_as_float(e0.y), acc);
        fma_bf16x4(x1, __uint_as_float(e1.y), acc);
    }
    if (e < end) {
        uint2 ed = __ldg(&g_edge[e]);
        uint2 x  = src[(size_t)ed.x * EMB4 + lane];
        fma_bf16x4(x, __uint_as_float(ed.y), acc);
    }
    size_t ri = (size_t)gw * EMB4 + lane;
    float4 a = (gw < N_USERS) ? ue[ri] : ie[ri - (size_t)N_USERS * EMB4];
    float4 b = bf16x4_to_f4(reinterpret_cast<const uint2*>(g_embh[1])[ri]);
    float4 c = bf16x4_to_f4(reinterpret_cast<const uint2*>(g_embh[2])[ri]);
    float4 comb;
    comb.x = ALPHA * (a.x + b.x + c.x + acc.x);
    comb.y = ALPHA * (a.y + b.y + c.y + acc.y);
    comb.z = ALPHA * (a.z + b.z + c.z + acc.z);
    comb.w = ALPHA * (a.w + b.w + c.w + acc.w);
    out[ri] = comb;                    // user_final / item_final (contiguous)
    if (gw < N_USERS) {
        float4 m = mask[ri];
        float4 mu = make_float4(comb.x * m.x, comb.y * m.y, comb.z * m.z, comb.w * m.w);
        out[O2_4 + ri] = mu;
        out[O4_4 + ri] = m;
    }
}

// ---------------- GEMM 128x128x16: predicted = relu(masked @ W + b) ---------
// Thread tile 8m x 8n; W smem granule-major with odd pad (2-way conflicts max);
// thread owns W granules {tx, tx+16} -> output cols [4tx,4tx+4) and [64+4tx,..).
__global__ void __launch_bounds__(256) k_gemm(const float* __restrict__ A,
                                              const float* __restrict__ W,
                                              const float* __restrict__ bias,
                                              float* __restrict__ C, int M) {
    __shared__ float  As[16][132];     // [k][m]
    __shared__ float4 Ws4[32 * 17];    // [granule][k] (+1 pad slot per granule)
    int tid = threadIdx.x;
    int m_base = blockIdx.x * 128;
    int tx = tid & 15;        // n granule index
    int ty = tid >> 4;        // m group: 8 rows each
    int m0 = ty * 8;
    unsigned long long acc2[8][4];
#pragma unroll
    for (int i = 0; i < 8; i++)
#pragma unroll
        for (int j = 0; j < 4; j++) acc2[i][j] = 0ull;

    for (int kk = 0; kk < 128; kk += 16) {
        // A tile: 128 rows x 16 k, transposed into As[k][m]
#pragma unroll
        for (int p = 0; p < 2; p++) {
            int idx = tid + p * 256;
            int row = idx >> 2;
            int c4  = (idx & 3) * 4;
            int gm  = m_base + row;
            float4 v = (gm < M) ? *reinterpret_cast<const float4*>(&A[(size_t)gm * 128 + kk + c4])
                                : make_float4(0.f, 0.f, 0.f, 0.f);
            As[c4 + 0][row] = v.x; As[c4 + 1][row] = v.y;
            As[c4 + 2][row] = v.z; As[c4 + 3][row] = v.w;
        }
        // W tile: 16 k x 128 n, granule-major
#pragma unroll
        for (int p = 0; p < 2; p++) {
            int idx = tid + p * 256;
            int k  = idx >> 5;
            int n4 = idx & 31;
            Ws4[n4 * 17 + k] =
                *reinterpret_cast<const float4*>(&W[(size_t)(kk + k) * 128 + n4 * 4]);
        }
        __syncthreads();
#pragma unroll
        for (int k = 0; k < 16; k++) {
            float4 a0 = *reinterpret_cast<float4*>(&As[k][m0]);
            float4 a1 = *reinterpret_cast<float4*>(&As[k][m0 + 4]);
            ulonglong2 wA = *reinterpret_cast<ulonglong2*>(&Ws4[tx * 17 + k]);
            ulonglong2 wB = *reinterpret_cast<ulonglong2*>(&Ws4[(tx + 16) * 17 + k]);
            unsigned long long wv[4] = {wA.x, wA.y, wB.x, wB.y};
            unsigned long long av[8] = {pk2(a0.x), pk2(a0.y), pk2(a0.z), pk2(a0.w),
                                        pk2(a1.x), pk2(a1.y), pk2(a1.z), pk2(a1.w)};
#pragma unroll
            for (int i = 0; i < 8; i++)
#pragma unroll
                for (int j = 0; j < 4; j++)
                    ffma2(acc2[i][j], av[i], wv[j]);
        }
        __syncthreads();
    }
    int nA = tx * 4, nB = 64 + tx * 4;
    float bA[4], bB[4];
#pragma unroll
    for (int j = 0; j < 4; j++) { bA[j] = bias[nA + j]; bB[j] = bias[nB + j]; }
#pragma unroll
    for (int i = 0; i < 8; i++) {
        int gm = m_base + m0 + i;
        if (gm < M) {
            float2 p0 = upk2(acc2[i][0]);
            float2 p1 = upk2(acc2[i][1]);
            float2 p2 = upk2(acc2[i][2]);
            float2 p3 = upk2(acc2[i][3]);
            float4 r0, r1;
            r0.x = fmaxf(p0.x + bA[0], 0.f); r0.y = fmaxf(p0.y + bA[1], 0.f);
            r0.z = fmaxf(p1.x + bA[2], 0.f); r0.w = fmaxf(p1.y + bA[3], 0.f);
            r1.x = fmaxf(p2.x + bB[0], 0.f); r1.y = fmaxf(p2.y + bB[1], 0.f);
            r1.z = fmaxf(p3.x + bB[2], 0.f); r1.w = fmaxf(p3.y + bB[3], 0.f);
            *reinterpret_cast<float4*>(&C[(size_t)gm * 128 + nA]) = r0;
            *reinterpret_cast<float4*>(&C[(size_t)gm * 128 + nB]) = r1;
        }
    }
}

// ---------------- launch -----------------------------------------------------
extern "C" void kernel_launch(void* const* d_in, const int* in_sizes, int n_in,
                              void* d_out, int out_size) {
    const float* ue   = (const float*)d_in[0];
    const float* ie   = (const float*)d_in[1];
    const int*   rows = (const int*)  d_in[2];
    const int*   cols = (const int*)  d_in[3];
    const float* vals = (const float*)d_in[4];
    const float* mask = (const float*)d_in[5];
    const float* W    = (const float*)d_in[6];
    const float* bias = (const float*)d_in[7];
    float* out = (float*)d_out;

    int nthr = N_NODES * EMB4;  // 4.8M
    k_init<<<(nthr + 255) / 256, 256>>>((const float4*)ue, (const float4*)ie, rows);
    k_scan<<<SCAN_NB, 256>>>();
    k_scatter<<<(NNZ + 255) / 256, 256>>>(rows, cols, vals);
    k_spmm<<<(N_NODES * 32 + 255) / 256, 256>>>(0);
    k_spmm<<<(N_NODES * 32 + 255) / 256, 256>>>(1);
    k_final<<<(N_NODES * 32 + 255) / 256, 256>>>((const float4*)ue, (const float4*)ie,
                                                 (const float4*)mask, (float4*)out);

    const float* Amasked = out + (size_t)N_NODES * EMB;
    float* Cpred = out + (size_t)N_NODES * EMB + (size_t)N_USERS * EMB;
    k_gemm<<<(N_USERS + 127) / 128, 256>>>(Amasked, W, bias, Cpred, N_USERS);
}

// round 7
// speedup vs baseline: 1.5090x; 1.0089x over previous
#include <cuda_runtime.h>
#include <cuda_bf16.h>

#define N_USERS 100000
#define N_ITEMS 50000
#define N_NODES 150000
#define EMB     128
#define EMB4    32
#define NNZ     2400000
#define ALPHA   0.25f
#define SCAN_NB ((N_NODES + 255) / 256)

// ---------------- device scratch (static, no runtime allocation) ------------
// g_cnt zero-on-entry invariant: zeroed at load; k_scan re-zeroes after read.
// g_blkdesc reset each call by k_init (ordered before k_scan on the stream).
__device__ __align__(16) __nv_bfloat16  g_embh[3][(size_t)N_NODES * EMB]; // bf16 layers 0..2
__device__ int   g_cnt[N_NODES];
__device__ int   g_off[N_NODES + 1];
__device__ int   g_fill[N_NODES];
__device__ unsigned long long g_blkdesc[SCAN_NB]; // hi32: 0 inval,1 agg,2 incl; lo32 sum
__device__ uint2 g_edge[NNZ];                     // (col, float-bits of val)

// ---------------- helpers ----------------------------------------------------
__device__ __forceinline__ void fma_bf16x8(uint4 u, float v, float* acc) {
    __nv_bfloat162 b0 = *reinterpret_cast<const __nv_bfloat162*>(&u.x);
    __nv_bfloat162 b1 = *reinterpret_cast<const __nv_bfloat162*>(&u.y);
    __nv_bfloat162 b2 = *reinterpret_cast<const __nv_bfloat162*>(&u.z);
    __nv_bfloat162 b3 = *reinterpret_cast<const __nv_bfloat162*>(&u.w);
    float2 f0 = __bfloat1622float2(b0);
    float2 f1 = __bfloat1622float2(b1);
    float2 f2 = __bfloat1622float2(b2);
    float2 f3 = __bfloat1622float2(b3);
    acc[0] = fmaf(v, f0.x, acc[0]); acc[1] = fmaf(v, f0.y, acc[1]);
    acc[2] = fmaf(v, f1.x, acc[2]); acc[3] = fmaf(v, f1.y, acc[3]);
    acc[4] = fmaf(v, f2.x, acc[4]); acc[5] = fmaf(v, f2.y, acc[5]);
    acc[6] = fmaf(v, f3.x, acc[6]); acc[7] = fmaf(v, f3.y, acc[7]);
}

__device__ __forceinline__ void bf16x8_to_f8(uint4 u, float* f) {
    __nv_bfloat162 b0 = *reinterpret_cast<const __nv_bfloat162*>(&u.x);
    __nv_bfloat162 b1 = *reinterpret_cast<const __nv_bfloat162*>(&u.y);
    __nv_bfloat162 b2 = *reinterpret_cast<const __nv_bfloat162*>(&u.z);
    __nv_bfloat162 b3 = *reinterpret_cast<const __nv_bfloat162*>(&u.w);
    float2 f0 = __bfloat1622float2(b0);
    float2 f1 = __bfloat1622float2(b1);
    float2 f2 = __bfloat1622float2(b2);
    float2 f3 = __bfloat1622float2(b3);
    f[0] = f0.x; f[1] = f0.y; f[2] = f1.x; f[3] = f1.y;
    f[4] = f2.x; f[5] = f2.y; f[6] = f3.x; f[7] = f3.y;
}

__device__ __forceinline__ uint4 pack_bf16x8(const float* a) {
    uint4 r;
    __nv_bfloat162 h0 = __floats2bfloat162_rn(a[0], a[1]);
    __nv_bfloat162 h1 = __floats2bfloat162_rn(a[2], a[3]);
    __nv_bfloat162 h2 = __floats2bfloat162_rn(a[4], a[5]);
    __nv_bfloat162 h3 = __floats2bfloat162_rn(a[6], a[7]);
    r.x = *reinterpret_cast<const unsigned*>(&h0);
    r.y = *reinterpret_cast<const unsigned*>(&h1);
    r.z = *reinterpret_cast<const unsigned*>(&h2);
    r.w = *reinterpret_cast<const unsigned*>(&h3);
    return r;
}

__device__ __forceinline__ uint2 pack_bf16x4(float4 a) {
    uint2 r;
    __nv_bfloat162 h0 = __floats2bfloat162_rn(a.x, a.y);
    __nv_bfloat162 h1 = __floats2bfloat162_rn(a.z, a.w);
    r.x = *reinterpret_cast<const unsigned*>(&h0);
    r.y = *reinterpret_cast<const unsigned*>(&h1);
    return r;
}

// f32x2 packed math (sm_103a): 2 fp32 FMAs per instruction, exact fp32.
__device__ __forceinline__ unsigned long long pk2(float v) {
    unsigned long long r;
    asm("mov.b64 %0, {%1, %1};" : "=l"(r) : "f"(v));
    return r;
}
__device__ __forceinline__ void ffma2(unsigned long long& d,
                                      unsigned long long a, unsigned long long b) {
    asm("fma.rn.f32x2 %0, %1, %2, %0;" : "+l"(d) : "l"(a), "l"(b));
}
__device__ __forceinline__ float2 upk2(unsigned long long v) {
    float2 f;
    asm("mov.b64 {%0, %1}, %2;" : "=f"(f.x), "=f"(f.y) : "l"(v));
    return f;
}

// ---------------- init: bf16 layer-0 + fused edge histogram + scan reset ----
__global__ void k_init(const float4* __restrict__ ue, const float4* __restrict__ ie,
                       const int* __restrict__ rows) {
    int i = blockIdx.x * blockDim.x + threadIdx.x;
    if (i < SCAN_NB) g_blkdesc[i] = 0ull;
    if (i < NNZ) atomicAdd(&g_cnt[rows[i]], 1);   // g_cnt zero on entry (invariant)
    if (i >= N_NODES * EMB4) return;
    int node = i >> 5;
    float4 v = (node < N_USERS) ? ue[i] : ie[i - N_USERS * EMB4];
    reinterpret_cast<uint2*>(g_embh[0])[i] = pack_bf16x4(v);
}

// ---------------- single-pass scan (decoupled lookback) ----------------------
__global__ void __launch_bounds__(256) k_scan() {
    __shared__ int s[256];
    __shared__ int s_base;
    int tid = threadIdx.x, bid = blockIdx.x;
    int gid = bid * 256 + tid;
    int v = (gid < N_NODES) ? g_cnt[gid] : 0;
    if (gid < N_NODES) g_cnt[gid] = 0;            // restore zero invariant
    s[tid] = v;
    __syncthreads();
#pragma unroll
    for (int d = 1; d < 256; d <<= 1) {
        int t = (tid >= d) ? s[tid - d] : 0;
        __syncthreads();
        if (tid >= d) s[tid] += t;
        __syncthreads();
    }
    int incl = s[tid];
    int agg  = s[255];
    if (tid == 0) {
        unsigned long long w = ((bid == 0 ? 2ULL : 1ULL) << 32) | (unsigned)agg;
        atomicExch(&g_blkdesc[bid], w);
        if (bid == 0) s_base = 0;
    }
    if (bid > 0 && tid < 32) {
        int lane = tid;
        int exc = 0;
        int look = bid - 1;
        while (true) {
            int idx = look - lane;
            unsigned long long w;
            if (idx >= 0) {
                do { w = *(volatile unsigned long long*)&g_blkdesc[idx]; }
                while ((unsigned)(w >> 32) == 0u);
            } else {
                w = (2ULL << 32);
            }
            unsigned st = (unsigned)(w >> 32);
            int val = (int)(unsigned)w;
            unsigned bal = __ballot_sync(0xffffffffu, st == 2u);
            int first = __ffs(bal) - 1;             // closest inclusive (if any)
            int contrib = bal ? ((lane <= first) ? val : 0) : val;
#pragma unroll
            for (int o = 16; o; o >>= 1) contrib += __shfl_down_sync(0xffffffffu, contrib, o);
            contrib = __shfl_sync(0xffffffffu, contrib, 0);
            exc += contrib;
            if (bal) break;
            look -= 32;
        }
        if (lane == 0) {
            atomicExch(&g_blkdesc[bid], (2ULL << 32) | (unsigned)(exc + agg));
            s_base = exc;
        }
    }
    __syncthreads();
    int base = s_base;
    if (gid < N_NODES) {
        int o = base + incl - v;
        g_off[gid]  = o;
        g_fill[gid] = o;
    }
    if (gid == 0) g_off[N_NODES] = NNZ;
}

__global__ void k_scatter(const int* __restrict__ rows, const int* __restrict__ cols,
                          const float* __restrict__ vals) {
    int e = blockIdx.x * blockDim.x + threadIdx.x;
    if (e >= NNZ) return;
    int p = atomicAdd(&g_fill[rows[e]], 1);
    g_edge[p] = make_uint2((unsigned)cols[e], __float_as_uint(vals[e]));
}

// ---------------- SpMM: one warp per row, half-warp edge pairing ------------
// lanes 0-15 process even edges, 16-31 odd edges; each lane gathers uint4
// (8 bf16 dims). Cross-half shfl reduction at the end.
__global__ void __launch_bounds__(256) k_spmm(int layer) {
    int gw   = (blockIdx.x * 256 + threadIdx.x) >> 5;
    int lane = threadIdx.x & 31;
    if (gw >= N_NODES) return;
    int half = lane >> 4;            // 0 | 1
    unsigned hl = lane & 15;         // uint4 granule within row
    const uint4* __restrict__ src = reinterpret_cast<const uint4*>(g_embh[layer]);
    int beg = g_off[gw], end = g_off[gw + 1];
    float acc[8] = {0.f, 0.f, 0.f, 0.f, 0.f, 0.f, 0.f, 0.f};
    int e = beg;
    for (; e + 8 <= end; e += 8) {   // 4 pairs = 8 edges per batch
        uint2 ed[4]; uint4 x[4];
#pragma unroll
        for (int p = 0; p < 4; p++) ed[p] = __ldg(&g_edge[e + 2 * p + half]);
#pragma unroll
        for (int p = 0; p < 4; p++) x[p] = src[ed[p].x * 16u + hl];
#pragma unroll
        for (int p = 0; p < 4; p++) fma_bf16x8(x[p], __uint_as_float(ed[p].y), acc);
    }
    for (; e + 2 <= end; e += 2) {
        uint2 ed = __ldg(&g_edge[e + half]);
        uint4 x  = src[ed.x * 16u + hl];
        fma_bf16x8(x, __uint_as_float(ed.y), acc);
    }
    if (e < end) {                   // single leftover edge: half 0 only
        uint2 ed = __ldg(&g_edge[e]);
        uint4 x  = src[ed.x * 16u + hl];
        float v  = half ? 0.f : __uint_as_float(ed.y);
        fma_bf16x8(x, v, acc);
    }
#pragma unroll
    for (int d = 0; d < 8; d++)
        acc[d] += __shfl_xor_sync(0xffffffffu, acc[d], 16);
    if (half == 0)
        reinterpret_cast<uint4*>(g_embh[layer + 1])[(unsigned)gw * 16u + hl] = pack_bf16x8(acc);
}

// ---------------- final: SpMM layer 2->3 fused with combine + outputs -------
#define O2_4 ((size_t)N_NODES * EMB4)                       // masked_user
#define O3_4 (O2_4 + (size_t)N_USERS * EMB4)                // predicted
#define O4_4 (O3_4 + (size_t)N_USERS * EMB4)                // mask

__global__ void __launch_bounds__(256) k_final(const float4* __restrict__ ue,
                                               const float4* __restrict__ ie,
                                               const float4* __restrict__ mask,
                                               float4* __restrict__ out) {
    int gw   = (blockIdx.x * 256 + threadIdx.x) >> 5;
    int lane = threadIdx.x & 31;
    if (gw >= N_NODES) return;
    int half = lane >> 4;
    unsigned hl = lane & 15;
    const uint4* __restrict__ src = reinterpret_cast<const uint4*>(g_embh[2]);
    int beg = g_off[gw], end = g_off[gw + 1];
    float acc[8] = {0.f, 0.f, 0.f, 0.f, 0.f, 0.f, 0.f, 0.f};
    int e = beg;
    for (; e + 8 <= end; e += 8) {
        uint2 ed[4]; uint4 x[4];
#pragma unroll
        for (int p = 0; p < 4; p++) ed[p] = __ldg(&g_edge[e + 2 * p + half]);
#pragma unroll
        for (int p = 0; p < 4; p++) x[p] = src[ed[p].x * 16u + hl];
#pragma unroll
        for (int p = 0; p < 4; p++) fma_bf16x8(x[p], __uint_as_float(ed[p].y), acc);
    }
    for (; e + 2 <= end; e += 2) {
        uint2 ed = __ldg(&g_edge[e + half]);
        uint4 x  = src[ed.x * 16u + hl];
        fma_bf16x8(x, __uint_as_float(ed.y), acc);
    }
    if (e < end) {
        uint2 ed = __ldg(&g_edge[e]);
        uint4 x  = src[ed.x * 16u + hl];
        float v  = half ? 0.f : __uint_as_float(ed.y);
        fma_bf16x8(x, v, acc);
    }
#pragma unroll
    for (int d = 0; d < 8; d++)
        acc[d] += __shfl_xor_sync(0xffffffffu, acc[d], 16);
    if (half) return;

    // lanes 0-15 now own dims [8*hl, 8*hl+8) of the row
    unsigned g16 = (unsigned)gw * 16u + hl;       // uint4-granule index (bf16 rows)
    size_t   g32 = (size_t)gw * 32u + 2u * hl;    // float4-granule index (fp32 rows)
    float l0[8], l1[8], l2[8];
    {   // layer 0 exact from inputs
        float4 a0, a1;
        if (gw < N_USERS) { a0 = ue[g32]; a1 = ue[g32 + 1]; }
        else { size_t o = g32 - (size_t)N_USERS * 32u; a0 = ie[o]; a1 = ie[o + 1]; }
        l0[0]=a0.x; l0[1]=a0.y; l0[2]=a0.z; l0[3]=a0.w;
        l0[4]=a1.x; l0[5]=a1.y; l0[6]=a1.z; l0[7]=a1.w;
    }
    bf16x8_to_f8(reinterpret_cast<const uint4*>(g_embh[1])[g16], l1);
    bf16x8_to_f8(reinterpret_cast<const uint4*>(g_embh[2])[g16], l2);
    float comb[8];
#pragma unroll
    for (int d = 0; d < 8; d++)
        comb[d] = ALPHA * (l0[d] + l1[d] + l2[d] + acc[d]);
    float4 c0 = make_float4(comb[0], comb[1], comb[2], comb[3]);
    float4 c1 = make_float4(comb[4], comb[5], comb[6], comb[7]);
    out[g32]     = c0;                 // user_final / item_final (contiguous)
    out[g32 + 1] = c1;
    if (gw < N_USERS) {
        float4 m0 = mask[g32], m1 = mask[g32 + 1];
        out[O2_4 + g32]     = make_float4(c0.x*m0.x, c0.y*m0.y, c0.z*m0.z, c0.w*m0.w);
        out[O2_4 + g32 + 1] = make_float4(c1.x*m1.x, c1.y*m1.y, c1.z*m1.z, c1.w*m1.w);
        out[O4_4 + g32]     = m0;
        out[O4_4 + g32 + 1] = m1;
    }
}

// ---------------- GEMM 128x128x16: predicted = relu(masked @ W + b) ---------
__global__ void __launch_bounds__(256) k_gemm(const float* __restrict__ A,
                                              const float* __restrict__ W,
                                              const float* __restrict__ bias,
                                              float* __restrict__ C, int M) {
    __shared__ float  As[16][132];     // [k][m]
    __shared__ float4 Ws4[32 * 17];    // [granule][k] (+1 pad slot per granule)
    int tid = threadIdx.x;
    int m_base = blockIdx.x * 128;
    int tx = tid & 15;        // n granule index
    int ty = tid >> 4;        // m group: 8 rows each
    int m0 = ty * 8;
    unsigned long long acc2[8][4];
#pragma unroll
    for (int i = 0; i < 8; i++)
#pragma unroll
        for (int j = 0; j < 4; j++) acc2[i][j] = 0ull;

    for (int kk = 0; kk < 128; kk += 16) {
#pragma unroll
        for (int p = 0; p < 2; p++) {
            int idx = tid + p * 256;
            int row = idx >> 2;
            int c4  = (idx & 3) * 4;
            int gm  = m_base + row;
            float4 v = (gm < M) ? *reinterpret_cast<const float4*>(&A[(size_t)gm * 128 + kk + c4])
                                : make_float4(0.f, 0.f, 0.f, 0.f);
            As[c4 + 0][row] = v.x; As[c4 + 1][row] = v.y;
            As[c4 + 2][row] = v.z; As[c4 + 3][row] = v.w;
        }
#pragma unroll
        for (int p = 0; p < 2; p++) {
            int idx = tid + p * 256;
            int k  = idx >> 5;
            int n4 = idx & 31;
            Ws4[n4 * 17 + k] =
                *reinterpret_cast<const float4*>(&W[(size_t)(kk + k) * 128 + n4 * 4]);
        }
        __syncthreads();
#pragma unroll
        for (int k = 0; k < 16; k++) {
            float4 a0 = *reinterpret_cast<float4*>(&As[k][m0]);
            float4 a1 = *reinterpret_cast<float4*>(&As[k][m0 + 4]);
            ulonglong2 wA = *reinterpret_cast<ulonglong2*>(&Ws4[tx * 17 + k]);
            ulonglong2 wB = *reinterpret_cast<ulonglong2*>(&Ws4[(tx + 16) * 17 + k]);
            unsigned long long wv[4] = {wA.x, wA.y, wB.x, wB.y};
            unsigned long long av[8] = {pk2(a0.x), pk2(a0.y), pk2(a0.z), pk2(a0.w),
                                        pk2(a1.x), pk2(a1.y), pk2(a1.z), pk2(a1.w)};
#pragma unroll
            for (int i = 0; i < 8; i++)
#pragma unroll
                for (int j = 0; j < 4; j++)
                    ffma2(acc2[i][j], av[i], wv[j]);
        }
        __syncthreads();
    }
    int nA = tx * 4, nB = 64 + tx * 4;
    float bA[4], bB[4];
#pragma unroll
    for (int j = 0; j < 4; j++) { bA[j] = bias[nA + j]; bB[j] = bias[nB + j]; }
#pragma unroll
    for (int i = 0; i < 8; i++) {
        int gm = m_base + m0 + i;
        if (gm < M) {
            float2 p0 = upk2(acc2[i][0]);
            float2 p1 = upk2(acc2[i][1]);
            float2 p2 = upk2(acc2[i][2]);
            float2 p3 = upk2(acc2[i][3]);
            float4 r0, r1;
            r0.x = fmaxf(p0.x + bA[0], 0.f); r0.y = fmaxf(p0.y + bA[1], 0.f);
            r0.z = fmaxf(p1.x + bA[2], 0.f); r0.w = fmaxf(p1.y + bA[3], 0.f);
            r1.x = fmaxf(p2.x + bB[0], 0.f); r1.y = fmaxf(p2.y + bB[1], 0.f);
            r1.z = fmaxf(p3.x + bB[2], 0.f); r1.w = fmaxf(p3.y + bB[3], 0.f);
            *reinterpret_cast<float4*>(&C[(size_t)gm * 128 + nA]) = r0;
            *reinterpret_cast<float4*>(&C[(size_t)gm * 128 + nB]) = r1;
        }
    }
}

// ---------------- launch -----------------------------------------------------
extern "C" void kernel_launch(void* const* d_in, const int* in_sizes, int n_in,
                              void* d_out, int out_size) {
    const float* ue   = (const float*)d_in[0];
    const float* ie   = (const float*)d_in[1];
    const int*   rows = (const int*)  d_in[2];
    const int*   cols = (const int*)  d_in[3];
    const float* vals = (const float*)d_in[4];
    const float* mask = (const float*)d_in[5];
    const float* W    = (const float*)d_in[6];
    const float* bias = (const float*)d_in[7];
    float* out = (float*)d_out;

    int nthr = N_NODES * EMB4;  // 4.8M
    k_init<<<(nthr + 255) / 256, 256>>>((const float4*)ue, (const float4*)ie, rows);
    k_scan<<<SCAN_NB, 256>>>();
    k_scatter<<<(NNZ + 255) / 256, 256>>>(rows, cols, vals);
    k_spmm<<<(N_NODES * 32 + 255) / 256, 256>>>(0);
    k_spmm<<<(N_NODES * 32 + 255) / 256, 256>>>(1);
    k_final<<<(N_NODES * 32 + 255) / 256, 256>>>((const float4*)ue, (const float4*)ie,
                                                 (const float4*)mask, (float4*)out);

    const float* Amasked = out + (size_t)N_NODES * EMB;
    float* Cpred = out + (size_t)N_NODES * EMB + (size_t)N_USERS * EMB;
    k_gemm<<<(N_USERS + 127) / 128, 256>>>(Amasked, W, bias, Cpred, N_USERS);
}